// round 12
// baseline (speedup 1.0000x reference)
#include <cuda_runtime.h>
#include <cuda_bf16.h>
#include <cstdint>
#include <math.h>

#define Bsz 256
#define Tt  512
#define Din 256
#define Hh  512
#define G4  2048
#define NC  128

// phase-1 pipeline params (unchanged, validated)
#define STAGES 4
#define KC     32
#define PADW   36    // 32+4 pad -> conflict-free fragment loads

// recurrence params (mma.sync, 128 threads/CTA, 128 CTAs)
#define NSTG   4
#define RKC    64
#define PADW2  68    // 64+4 pad
#define WPAD   516   // 512+4 pad
#define SMA_SZ (NSTG*64*PADW2*4)        // 69632
#define SMW_OFF SMA_SZ                   // W slice at 69632
#define SMP_OFF (SMW_OFF + 64*WPAD*4)    // 201728
#define SMEM_REC (SMP_OFF + 64*64*4)     // 218112 bytes
#define NGRP   32

// ---------------- static device scratch (no allocations allowed) ----------------
__device__ __align__(128) float g_P[(size_t)Tt * Bsz * G4];   // x-projection + biases, [t][b][g]
__device__ __align__(128) float g_xr[(size_t)Bsz * Tt * Din]; // tf32-rounded x
__device__ __align__(128) float g_Wih[G4 * Din];              // tf32-rounded W_ih
__device__ __align__(128) float g_Whh[G4 * Hh];               // tf32-rounded W_hh
__device__ __align__(128) float g_h[3][Bsz * Hh];             // 3-deep ring (fine-grained sync safety)

// per (b-group, k-chunk) producer signals; each on its own 128B line.
// g_sig[grp][c][0] counts completed epilogues (4 producers per chunk per step).
__device__ __align__(128) unsigned g_sig[4][8][32];

// ---------------- helpers ----------------
__device__ __forceinline__ float rtf(float x) {
    unsigned u;
    asm("cvt.rna.tf32.f32 %0, %1;" : "=r"(u) : "f"(x));
    return __uint_as_float(u);
}

__device__ __forceinline__ void mma_tf32(float (&c)[4], const unsigned (&a)[4],
                                         unsigned b0, unsigned b1) {
    asm volatile(
        "mma.sync.aligned.m16n8k8.row.col.f32.tf32.tf32.f32 "
        "{%0,%1,%2,%3}, {%4,%5,%6,%7}, {%8,%9}, {%0,%1,%2,%3};\n"
        : "+f"(c[0]), "+f"(c[1]), "+f"(c[2]), "+f"(c[3])
        : "r"(a[0]), "r"(a[1]), "r"(a[2]), "r"(a[3]), "r"(b0), "r"(b1));
}

__device__ __forceinline__ void cpa16(uint32_t s, const void* g) {
    asm volatile("cp.async.cg.shared.global [%0], [%1], 16;\n" :: "r"(s), "l"(g));
}
__device__ __forceinline__ void cpa_commit() {
    asm volatile("cp.async.commit_group;\n");
}
template<int N> __device__ __forceinline__ void cpa_wait() {
    asm volatile("cp.async.wait_group %0;\n" :: "n"(N));
}

__device__ __forceinline__ float sigm(float x) { return 1.f / (1.f + __expf(-x)); }
__device__ __forceinline__ float tanh_fast(float x) { return 1.f - 2.f / (__expf(2.f * x) + 1.f); }

// ---------------- prep: round inputs to tf32, zero state, reset signals ----------------
__global__ void prep_kernel(const float* __restrict__ x,
                            const float* __restrict__ Wih,
                            const float* __restrict__ Whh) {
    size_t i = (size_t)blockIdx.x * blockDim.x + threadIdx.x;
    size_t stride = (size_t)gridDim.x * blockDim.x;
    if (i == 0) {
        for (int g = 0; g < 4; g++)
            for (int c = 0; c < 8; c++) g_sig[g][c][0] = 0;
    }
    for (size_t k = i; k < (size_t)Bsz * Tt * Din; k += stride) g_xr[k]  = rtf(x[k]);
    for (size_t k = i; k < (size_t)G4 * Din;       k += stride) g_Wih[k] = rtf(Wih[k]);
    for (size_t k = i; k < (size_t)G4 * Hh;        k += stride) g_Whh[k] = rtf(Whh[k]);
    for (size_t k = i; k < (size_t)Bsz * Hh;       k += stride) g_h[0][k] = 0.f;
}

// ---------------- phase 1 (unchanged, validated) ----------------
__global__ void __launch_bounds__(256) phase1_kernel(const float* __restrict__ bih,
                                                     const float* __restrict__ bhh) {
    extern __shared__ float sm[];
    float* sA = sm;
    float* sB = sm + STAGES * 64 * PADW;
    uint32_t smem_u32 = (uint32_t)__cvta_generic_to_shared(sm);
    uint32_t sA_b = smem_u32;
    uint32_t sB_b = smem_u32 + STAGES * 64 * PADW * 4;

    const int tid = threadIdx.x;
    const int g0 = blockIdx.x * 128;
    const int r0 = blockIdx.y * 64;
    const int NCH = Din / KC;  // 8

    auto load_chunk = [&](int kk, int stage) {
        const int kb = kk * KC;
#pragma unroll
        for (int i = 0; i < 2; i++) {
            int v = tid + i * 256;
            int row = v >> 3, q = v & 7;
            int r = r0 + row;
            int b = r & 255, t = r >> 8;
            const float* src = g_xr + ((size_t)b * Tt + t) * Din + kb + q * 4;
            cpa16(sA_b + (uint32_t)((stage * 64 * PADW + row * PADW + q * 4) * 4), src);
        }
#pragma unroll
        for (int i = 0; i < 4; i++) {
            int v = tid + i * 256;
            int r = v >> 3, q = v & 7;
            const float* src = g_Wih + (size_t)(g0 + r) * Din + kb + q * 4;
            cpa16(sB_b + (uint32_t)((stage * 128 * PADW + r * PADW + q * 4) * 4), src);
        }
        cpa_commit();
    };

    const int lane = tid & 31, wid = tid >> 5;
    const int gid = lane >> 2, tig = lane & 3;
    const int m0 = (wid >> 2) * 32, n0 = (wid & 3) * 32;

    float acc[2][4][4] = {};

    load_chunk(0, 0); load_chunk(1, 1); load_chunk(2, 2);
    for (int kk = 0; kk < NCH; kk++) {
        if (kk < NCH - 2)       cpa_wait<2>();
        else if (kk == NCH - 2) cpa_wait<1>();
        else                    cpa_wait<0>();
        __syncthreads();
        if (kk + 3 < NCH) load_chunk(kk + 3, (kk + 3) % STAGES);

        const float* cA = sA + (kk % STAGES) * 64 * PADW;
        const float* cB = sB + (kk % STAGES) * 128 * PADW;
#pragma unroll
        for (int k8 = 0; k8 < KC / 8; k8++) {
            const int kb = k8 * 8;
            unsigned a[2][4];
#pragma unroll
            for (int mt = 0; mt < 2; mt++) {
                int r = m0 + mt * 16 + gid;
                a[mt][0] = __float_as_uint(cA[r * PADW + kb + tig]);
                a[mt][1] = __float_as_uint(cA[(r + 8) * PADW + kb + tig]);
                a[mt][2] = __float_as_uint(cA[r * PADW + kb + tig + 4]);
                a[mt][3] = __float_as_uint(cA[(r + 8) * PADW + kb + tig + 4]);
            }
#pragma unroll
            for (int nt = 0; nt < 4; nt++) {
                int cr = n0 + nt * 8 + gid;
                unsigned b0 = __float_as_uint(cB[cr * PADW + kb + tig]);
                unsigned b1 = __float_as_uint(cB[cr * PADW + kb + tig + 4]);
                mma_tf32(acc[0][nt], a[0], b0, b1);
                mma_tf32(acc[1][nt], a[1], b0, b1);
            }
        }
    }

#pragma unroll
    for (int nt = 0; nt < 4; nt++) {
        int col = n0 + nt * 8 + tig * 2;
        float bv0 = bih[g0 + col] + bhh[g0 + col];
        float bv1 = bih[g0 + col + 1] + bhh[g0 + col + 1];
#pragma unroll
        for (int mt = 0; mt < 2; mt++) {
            int row = m0 + mt * 16 + gid;
            float2 v0 = make_float2(acc[mt][nt][0] + bv0, acc[mt][nt][1] + bv1);
            float2 v1 = make_float2(acc[mt][nt][2] + bv0, acc[mt][nt][3] + bv1);
            *reinterpret_cast<float2*>(&g_P[(size_t)(r0 + row) * G4 + g0 + col]) = v0;
            *reinterpret_cast<float2*>(&g_P[(size_t)(r0 + row + 8) * G4 + g0 + col]) = v1;
        }
    }
}

// ---------------- persistent LSTM recurrence (mma.sync, fine-grained sync) ----------------
// 128 CTAs (32 j-tiles of 16 x 4 b-tiles of 64), 128 threads (4 warps, 2x2 grid of
// 32x32 warp tiles -> 33% less fragment-LDS than 8x(32x16)). W slice persistent in
// SMEM. h in a 3-deep global ring. Producer/consumer chunk signaling replaces the
// full group barrier: chunk c of step t needs only its 4 producer CTAs' step-(t-1)
// signals (sig >= 4t). P tile staged to SMEM via its own cp.async group.
__global__ void __launch_bounds__(128) lstm_persist() {
    extern __shared__ float sm[];
    float* sA = sm;                              // NSTG x 64 x PADW2 (G reuses)
    float* sW = sm + NSTG * 64 * PADW2;          // 64 x WPAD persistent W slice
    float* sP = sm + SMP_OFF / 4;                // 64 x 64 P tile
    uint32_t sb = (uint32_t)__cvta_generic_to_shared(sm);

    const int tid = threadIdx.x;
    const int lane = tid & 31, wid = tid >> 5;
    const int gid = lane >> 2, tig = lane & 3;
    const int m0 = (wid >> 1) * 32, n0 = (wid & 1) * 32;   // 2x2 warp grid
    const int j0 = blockIdx.x * 16;
    const int b0 = blockIdx.y * 64;
    const int grp = blockIdx.y;
    const int jg = blockIdx.x >> 2;              // this CTA's chunk-producer group

    // one-time: W slice [64 rows x 512], row = gate*16 + jj
    for (int v = tid; v < 64 * 128; v += 128) {
        int r = v >> 7, q = v & 127;
        int gate = r >> 4, jj = r & 15;
        float4 s = *reinterpret_cast<const float4*>(
            g_Whh + (size_t)(gate * Hh + j0 + jj) * Hh + q * 4);
        *reinterpret_cast<float4*>(&sW[r * WPAD + q * 4]) = s;
    }
    __syncthreads();

    float creg[8] = {};          // register-resident cell state
    int hb = 0;                  // t % 3

    for (int t = 0; t < Tt; t++) {
        const float* __restrict__ hprev = g_h[hb];
        int hbn = (hb == 2) ? 0 : hb + 1;
        float* __restrict__ hnext = g_h[hbn];
        const float* __restrict__ Pt = g_P + (size_t)t * Bsz * G4;

        // async P tile -> sP (oldest cp.async group this step; done by chunk 0's wait)
#pragma unroll
        for (int i = 0; i < 8; i++) {
            int v = i * 128 + tid;
            int bl = v >> 4, gate = (v >> 2) & 3, qj = v & 3;
            const float* src = Pt + (size_t)(b0 + bl) * G4 + gate * 512 + j0 + qj * 4;
            cpa16(sb + (uint32_t)(SMP_OFF + (bl * 64 + gate * 16 + qj * 4) * 4), src);
        }
        cpa_commit();

        auto sigw = [&](int c) {     // wait chunk c's 4 producers (monotonic counters)
            unsigned target = 4u * (unsigned)t;
            if (target)
                while (*(volatile unsigned*)&g_sig[grp][c][0] < target) __nanosleep(64);
        };
        auto loadA = [&](int c, int stg) {   // stage h chunk: 64 rows x 64 f32
            const int kb = c * RKC;
#pragma unroll
            for (int i = 0; i < 8; i++) {
                int v = i * 128 + tid;
                int r = v >> 4, q = v & 15;
                const float* src = hprev + (size_t)(b0 + r) * Hh + kb + q * 4;
                cpa16(sb + (uint32_t)((stg * 64 * PADW2 + r * PADW2 + q * 4) * 4), src);
            }
            cpa_commit();
        };

        sigw(0); loadA(0, 0); sigw(1); loadA(1, 1); sigw(2); loadA(2, 2);

        float acc[2][4][4] = {};
        for (int kk = 0; kk < 8; kk++) {
            if (kk < 6)       cpa_wait<2>();
            else if (kk == 6) cpa_wait<1>();
            else              cpa_wait<0>();
            __syncthreads();
            if (kk < 5) { sigw(kk + 3); loadA(kk + 3, (kk + 3) & 3); }

            const float* cA = sA + (kk & 3) * 64 * PADW2;
            const float* cW = sW + kk * RKC;
#pragma unroll
            for (int k8 = 0; k8 < 8; k8++) {
                const int kb = k8 * 8;
                unsigned a[2][4];
#pragma unroll
                for (int mt = 0; mt < 2; mt++) {
                    int r = m0 + mt * 16 + gid;
                    a[mt][0] = __float_as_uint(cA[r * PADW2 + kb + tig]);
                    a[mt][1] = __float_as_uint(cA[(r + 8) * PADW2 + kb + tig]);
                    a[mt][2] = __float_as_uint(cA[r * PADW2 + kb + tig + 4]);
                    a[mt][3] = __float_as_uint(cA[(r + 8) * PADW2 + kb + tig + 4]);
                }
#pragma unroll
                for (int nt = 0; nt < 4; nt++) {
                    int cr = n0 + nt * 8 + gid;
                    unsigned b0r = __float_as_uint(cW[cr * WPAD + kb + tig]);
                    unsigned b1r = __float_as_uint(cW[cr * WPAD + kb + tig + 4]);
                    mma_tf32(acc[0][nt], a[0], b0r, b1r);
                    mma_tf32(acc[1][nt], a[1], b0r, b1r);
                }
            }
        }

        __syncthreads();         // GEMM done; reuse sA region as G[64][68]
        float* G = sm;
#pragma unroll
        for (int mt = 0; mt < 2; mt++)
#pragma unroll
            for (int nt = 0; nt < 4; nt++) {
                int row = m0 + mt * 16 + gid, col = n0 + nt * 8 + tig * 2;
                G[row * 68 + col]           = acc[mt][nt][0];
                G[row * 68 + col + 1]       = acc[mt][nt][1];
                G[(row + 8) * 68 + col]     = acc[mt][nt][2];
                G[(row + 8) * 68 + col + 1] = acc[mt][nt][3];
            }
        __syncthreads();

        // elementwise update: 64 b x 16 j = 1024 pairs, 8 per thread
#pragma unroll
        for (int e = 0; e < 8; e++) {
            int idx = e * 128 + tid;
            int bl = idx >> 4, jl = idx & 15;
            float pi = G[bl * 68 + jl]      + sP[bl * 64 + jl];
            float pf = G[bl * 68 + 16 + jl] + sP[bl * 64 + 16 + jl];
            float pg = G[bl * 68 + 32 + jl] + sP[bl * 64 + 32 + jl];
            float po = G[bl * 68 + 48 + jl] + sP[bl * 64 + 48 + jl];
            float ig = sigm(pi);
            float fg = sigm(pf);
            float gg = tanh_fast(pg);
            float og = sigm(po);
            float cn = fg * creg[e] + ig * gg;
            creg[e] = cn;
            hnext[(size_t)(b0 + bl) * Hh + j0 + jl] = rtf(og * tanh_fast(cn));
        }

        if (t != Tt - 1) {
            __syncthreads();     // all h stores of this CTA done
            if (tid == 0) {
                __threadfence(); // h stores -> L2 before signal
                atomicAdd(&g_sig[grp][jg][0], 1u);
            }
        }
        hb = hbn;
    }
}

// ---------------- final FC: out[b][n] = h_last[b,:]·W_fc[n,:] + b_fc[n] ----------------
__global__ void fc_kernel(const float* __restrict__ Wfc,
                          const float* __restrict__ bfc,
                          float* __restrict__ out) {
    int w = (blockIdx.x * blockDim.x + threadIdx.x) >> 5;
    int lane = threadIdx.x & 31;
    int b = w >> 7, n = w & 127;
    const float* hr = g_h[2] + (size_t)b * Hh;              // t=511 wrote g_h[512%3=2]
    const float* wr = Wfc + (size_t)n * Hh;
    float s = 0.f;
    for (int k = lane; k < Hh; k += 32) s += hr[k] * wr[k];
#pragma unroll
    for (int off = 16; off; off >>= 1) s += __shfl_xor_sync(0xffffffffu, s, off);
    if (lane == 0) out[b * NC + n] = s + bfc[n];
}

// ---------------- launch ----------------
extern "C" void kernel_launch(void* const* d_in, const int* in_sizes, int n_in,
                              void* d_out, int out_size) {
    (void)in_sizes; (void)n_in; (void)out_size;
    const float* x   = (const float*)d_in[0];
    const float* Wih = (const float*)d_in[1];
    const float* Whh = (const float*)d_in[2];
    const float* bih = (const float*)d_in[3];
    const float* bhh = (const float*)d_in[4];
    const float* Wfc = (const float*)d_in[5];
    const float* bfc = (const float*)d_in[6];
    float* out = (float*)d_out;

    const int smem_p1 = STAGES * (64 + 128) * PADW * 4;   // 110592
    cudaFuncSetAttribute(phase1_kernel, cudaFuncAttributeMaxDynamicSharedMemorySize, smem_p1);
    cudaFuncSetAttribute(lstm_persist,  cudaFuncAttributeMaxDynamicSharedMemorySize, SMEM_REC);

    prep_kernel<<<2048, 256>>>(x, Wih, Whh);
    phase1_kernel<<<dim3(16, 2048), 256, smem_p1>>>(bih, bhh);
    lstm_persist<<<dim3(32, 4), 128, SMEM_REC>>>();
    fc_kernel<<<4096, 256>>>(Wfc, bfc, out);
}

// round 15
// speedup vs baseline: 1.0717x; 1.0717x over previous
#include <cuda_runtime.h>
#include <cuda_bf16.h>
#include <cstdint>
#include <math.h>

#define Bsz 256
#define Tt  512
#define Din 256
#define Hh  512
#define G4  2048
#define NC  128

// phase-1 pipeline params (unchanged, validated)
#define STAGES 4
#define KC     32
#define PADW   36    // 32+4 pad -> conflict-free fragment loads

// recurrence params (mma.sync, 256 threads/CTA, 128 CTAs)
#define NSTG   4
#define RKC    64
#define PADW2  68    // 64+4 pad
#define WPAD   516   // 512+4 pad
#define SMA_SZ (NSTG*64*PADW2*4)        // 69632
#define SMW_OFF SMA_SZ                   // W slice at 69632
#define SMP_OFF (SMW_OFF + 64*WPAD*4)    // 201728
#define SMEM_REC (SMP_OFF + 64*64*4)     // 218112 bytes

// ---------------- static device scratch (no allocations allowed) ----------------
__device__ __align__(128) float g_P[(size_t)Tt * Bsz * G4];   // x-projection + biases, [t][b][g]
__device__ __align__(128) float g_xr[(size_t)Bsz * Tt * Din]; // tf32-rounded x
__device__ __align__(128) float g_Wih[G4 * Din];              // tf32-rounded W_ih
__device__ __align__(128) float g_Whh[G4 * Hh];              // tf32-rounded W_hh
__device__ __align__(128) float g_h[3][Bsz * Hh];             // 3-deep ring (fine-grained sync safety)

// per (b-group, k-chunk) producer signals; each on its own 128B line.
// g_sig[grp][c][0] counts completed epilogues (4 producers per chunk per step).
__device__ __align__(128) unsigned g_sig[4][8][32];

// ---------------- helpers ----------------
__device__ __forceinline__ float rtf(float x) {
    unsigned u;
    asm("cvt.rna.tf32.f32 %0, %1;" : "=r"(u) : "f"(x));
    return __uint_as_float(u);
}

__device__ __forceinline__ void mma_tf32(float (&c)[4], const unsigned (&a)[4],
                                         unsigned b0, unsigned b1) {
    asm volatile(
        "mma.sync.aligned.m16n8k8.row.col.f32.tf32.tf32.f32 "
        "{%0,%1,%2,%3}, {%4,%5,%6,%7}, {%8,%9}, {%0,%1,%2,%3};\n"
        : "+f"(c[0]), "+f"(c[1]), "+f"(c[2]), "+f"(c[3])
        : "r"(a[0]), "r"(a[1]), "r"(a[2]), "r"(a[3]), "r"(b0), "r"(b1));
}

__device__ __forceinline__ void cpa16(uint32_t s, const void* g) {
    asm volatile("cp.async.cg.shared.global [%0], [%1], 16;\n" :: "r"(s), "l"(g));
}
__device__ __forceinline__ void cpa_commit() {
    asm volatile("cp.async.commit_group;\n");
}
template<int N> __device__ __forceinline__ void cpa_wait() {
    asm volatile("cp.async.wait_group %0;\n" :: "n"(N));
}

__device__ __forceinline__ float sigm(float x) { return 1.f / (1.f + __expf(-x)); }
__device__ __forceinline__ float tanh_fast(float x) { return 1.f - 2.f / (__expf(2.f * x) + 1.f); }

// ---------------- prep: round inputs to tf32, zero state, reset signals ----------------
__global__ void prep_kernel(const float* __restrict__ x,
                            const float* __restrict__ Wih,
                            const float* __restrict__ Whh) {
    size_t i = (size_t)blockIdx.x * blockDim.x + threadIdx.x;
    size_t stride = (size_t)gridDim.x * blockDim.x;
    if (i == 0) {
        for (int g = 0; g < 4; g++)
            for (int c = 0; c < 8; c++) g_sig[g][c][0] = 0;
    }
    for (size_t k = i; k < (size_t)Bsz * Tt * Din; k += stride) g_xr[k]  = rtf(x[k]);
    for (size_t k = i; k < (size_t)G4 * Din;       k += stride) g_Wih[k] = rtf(Wih[k]);
    for (size_t k = i; k < (size_t)G4 * Hh;        k += stride) g_Whh[k] = rtf(Whh[k]);
    for (size_t k = i; k < (size_t)Bsz * Hh;       k += stride) g_h[0][k] = 0.f;
}

// ---------------- phase 1 (unchanged, validated) ----------------
__global__ void __launch_bounds__(256) phase1_kernel(const float* __restrict__ bih,
                                                     const float* __restrict__ bhh) {
    extern __shared__ float sm[];
    float* sA = sm;
    float* sB = sm + STAGES * 64 * PADW;
    uint32_t smem_u32 = (uint32_t)__cvta_generic_to_shared(sm);
    uint32_t sA_b = smem_u32;
    uint32_t sB_b = smem_u32 + STAGES * 64 * PADW * 4;

    const int tid = threadIdx.x;
    const int g0 = blockIdx.x * 128;
    const int r0 = blockIdx.y * 64;
    const int NCH = Din / KC;  // 8

    auto load_chunk = [&](int kk, int stage) {
        const int kb = kk * KC;
#pragma unroll
        for (int i = 0; i < 2; i++) {
            int v = tid + i * 256;
            int row = v >> 3, q = v & 7;
            int r = r0 + row;
            int b = r & 255, t = r >> 8;
            const float* src = g_xr + ((size_t)b * Tt + t) * Din + kb + q * 4;
            cpa16(sA_b + (uint32_t)((stage * 64 * PADW + row * PADW + q * 4) * 4), src);
        }
#pragma unroll
        for (int i = 0; i < 4; i++) {
            int v = tid + i * 256;
            int r = v >> 3, q = v & 7;
            const float* src = g_Wih + (size_t)(g0 + r) * Din + kb + q * 4;
            cpa16(sB_b + (uint32_t)((stage * 128 * PADW + r * PADW + q * 4) * 4), src);
        }
        cpa_commit();
    };

    const int lane = tid & 31, wid = tid >> 5;
    const int gid = lane >> 2, tig = lane & 3;
    const int m0 = (wid >> 2) * 32, n0 = (wid & 3) * 32;

    float acc[2][4][4] = {};

    load_chunk(0, 0); load_chunk(1, 1); load_chunk(2, 2);
    for (int kk = 0; kk < NCH; kk++) {
        if (kk < NCH - 2)       cpa_wait<2>();
        else if (kk == NCH - 2) cpa_wait<1>();
        else                    cpa_wait<0>();
        __syncthreads();
        if (kk + 3 < NCH) load_chunk(kk + 3, (kk + 3) % STAGES);

        const float* cA = sA + (kk % STAGES) * 64 * PADW;
        const float* cB = sB + (kk % STAGES) * 128 * PADW;
#pragma unroll
        for (int k8 = 0; k8 < KC / 8; k8++) {
            const int kb = k8 * 8;
            unsigned a[2][4];
#pragma unroll
            for (int mt = 0; mt < 2; mt++) {
                int r = m0 + mt * 16 + gid;
                a[mt][0] = __float_as_uint(cA[r * PADW + kb + tig]);
                a[mt][1] = __float_as_uint(cA[(r + 8) * PADW + kb + tig]);
                a[mt][2] = __float_as_uint(cA[r * PADW + kb + tig + 4]);
                a[mt][3] = __float_as_uint(cA[(r + 8) * PADW + kb + tig + 4]);
            }
#pragma unroll
            for (int nt = 0; nt < 4; nt++) {
                int cr = n0 + nt * 8 + gid;
                unsigned b0 = __float_as_uint(cB[cr * PADW + kb + tig]);
                unsigned b1 = __float_as_uint(cB[cr * PADW + kb + tig + 4]);
                mma_tf32(acc[0][nt], a[0], b0, b1);
                mma_tf32(acc[1][nt], a[1], b0, b1);
            }
        }
    }

#pragma unroll
    for (int nt = 0; nt < 4; nt++) {
        int col = n0 + nt * 8 + tig * 2;
        float bv0 = bih[g0 + col] + bhh[g0 + col];
        float bv1 = bih[g0 + col + 1] + bhh[g0 + col + 1];
#pragma unroll
        for (int mt = 0; mt < 2; mt++) {
            int row = m0 + mt * 16 + gid;
            float2 v0 = make_float2(acc[mt][nt][0] + bv0, acc[mt][nt][1] + bv1);
            float2 v1 = make_float2(acc[mt][nt][2] + bv0, acc[mt][nt][3] + bv1);
            *reinterpret_cast<float2*>(&g_P[(size_t)(r0 + row) * G4 + g0 + col]) = v0;
            *reinterpret_cast<float2*>(&g_P[(size_t)(r0 + row + 8) * G4 + g0 + col]) = v1;
        }
    }
}

// ---------------- persistent LSTM recurrence ----------------
// 128 CTAs (32 j-tiles of 16 x 4 b-tiles of 64), 256 threads (8 warps, 2x4 grid of
// 32x16 warp tiles -> 2 warps/SMSP for latency hiding; R7-validated layout).
// W slice persistent in SMEM. h in a 3-deep global ring. Producer/consumer chunk
// signaling: chunk c of step t waits only for its 4 producer CTAs (sig >= 4t),
// so stragglers hide behind the 8-chunk pipeline instead of a full-group barrier.
// P tile staged to SMEM via its own cp.async group (cold-DRAM latency async).
__global__ void __launch_bounds__(256) lstm_persist() {
    extern __shared__ float sm[];
    float* sA = sm;                              // NSTG x 64 x PADW2 (G reuses)
    float* sW = sm + NSTG * 64 * PADW2;          // 64 x WPAD persistent W slice
    float* sP = sm + SMP_OFF / 4;                // 64 x 64 P tile
    uint32_t sb = (uint32_t)__cvta_generic_to_shared(sm);

    const int tid = threadIdx.x;
    const int lane = tid & 31, wid = tid >> 5;
    const int gid = lane >> 2, tig = lane & 3;
    const int m0 = (wid >> 2) * 32;              // 2 m-tiles of 32
    const int n0 = (wid & 3) * 16;               // 4 n-tiles of 16
    const int j0 = blockIdx.x * 16;
    const int b0 = blockIdx.y * 64;
    const int grp = blockIdx.y;
    const int jg = blockIdx.x >> 2;              // this CTA's chunk-producer group

    // one-time: W slice [64 rows x 512], row = gate*16 + jj
    for (int v = tid; v < 64 * 128; v += 256) {
        int r = v >> 7, q = v & 127;
        int gate = r >> 4, jj = r & 15;
        float4 s = *reinterpret_cast<const float4*>(
            g_Whh + (size_t)(gate * Hh + j0 + jj) * Hh + q * 4);
        *reinterpret_cast<float4*>(&sW[r * WPAD + q * 4]) = s;
    }
    __syncthreads();

    float creg[4] = {};          // register-resident cell state
    int hb = 0;                  // t % 3

    for (int t = 0; t < Tt; t++) {
        const float* __restrict__ hprev = g_h[hb];
        int hbn = (hb == 2) ? 0 : hb + 1;
        float* __restrict__ hnext = g_h[hbn];
        const float* __restrict__ Pt = g_P + (size_t)t * Bsz * G4;

        // async P tile -> sP (oldest cp.async group this step; done by chunk 0's wait)
#pragma unroll
        for (int i = 0; i < 4; i++) {
            int v = i * 256 + tid;
            int bl = v >> 4, gate = (v >> 2) & 3, qj = v & 3;
            const float* src = Pt + (size_t)(b0 + bl) * G4 + gate * 512 + j0 + qj * 4;
            cpa16(sb + (uint32_t)(SMP_OFF + (bl * 64 + gate * 16 + qj * 4) * 4), src);
        }
        cpa_commit();

        auto sigw = [&](int c) {     // wait chunk c's 4 producers (monotonic counters)
            unsigned target = 4u * (unsigned)t;
            if (target)
                while (*(volatile unsigned*)&g_sig[grp][c][0] < target) __nanosleep(64);
        };
        auto loadA = [&](int c, int stg) {   // stage h chunk: 64 rows x 64 f32
            const int kb = c * RKC;
#pragma unroll
            for (int i = 0; i < 4; i++) {
                int v = i * 256 + tid;
                int r = v >> 4, q = v & 15;
                const float* src = hprev + (size_t)(b0 + r) * Hh + kb + q * 4;
                cpa16(sb + (uint32_t)((stg * 64 * PADW2 + r * PADW2 + q * 4) * 4), src);
            }
            cpa_commit();
        };

        sigw(0); loadA(0, 0); sigw(1); loadA(1, 1); sigw(2); loadA(2, 2);

        float acc[2][2][4] = {};
        for (int kk = 0; kk < 8; kk++) {
            if (kk < 6)       cpa_wait<2>();
            else if (kk == 6) cpa_wait<1>();
            else              cpa_wait<0>();
            __syncthreads();
            if (kk < 5) { sigw(kk + 3); loadA(kk + 3, (kk + 3) & 3); }

            const float* cA = sA + (kk & 3) * 64 * PADW2;
            const float* cW = sW + kk * RKC;
#pragma unroll
            for (int k8 = 0; k8 < 8; k8++) {
                const int kb = k8 * 8;
                unsigned a[2][4];
#pragma unroll
                for (int mt = 0; mt < 2; mt++) {
                    int r = m0 + mt * 16 + gid;
                    a[mt][0] = __float_as_uint(cA[r * PADW2 + kb + tig]);
                    a[mt][1] = __float_as_uint(cA[(r + 8) * PADW2 + kb + tig]);
                    a[mt][2] = __float_as_uint(cA[r * PADW2 + kb + tig + 4]);
                    a[mt][3] = __float_as_uint(cA[(r + 8) * PADW2 + kb + tig + 4]);
                }
#pragma unroll
                for (int nt = 0; nt < 2; nt++) {
                    int cr = n0 + nt * 8 + gid;
                    unsigned b0r = __float_as_uint(cW[cr * WPAD + kb + tig]);
                    unsigned b1r = __float_as_uint(cW[cr * WPAD + kb + tig + 4]);
                    mma_tf32(acc[0][nt], a[0], b0r, b1r);
                    mma_tf32(acc[1][nt], a[1], b0r, b1r);
                }
            }
        }

        __syncthreads();         // GEMM done; reuse sA region as G[64][68]
        float* G = sm;
#pragma unroll
        for (int mt = 0; mt < 2; mt++)
#pragma unroll
            for (int nt = 0; nt < 2; nt++) {
                int row = m0 + mt * 16 + gid, col = n0 + nt * 8 + tig * 2;
                G[row * 68 + col]           = acc[mt][nt][0];
                G[row * 68 + col + 1]       = acc[mt][nt][1];
                G[(row + 8) * 68 + col]     = acc[mt][nt][2];
                G[(row + 8) * 68 + col + 1] = acc[mt][nt][3];
            }
        __syncthreads();

        // elementwise update: 64 b x 16 j = 1024 pairs, 4 per thread
#pragma unroll
        for (int e = 0; e < 4; e++) {
            int idx = e * 256 + tid;
            int bl = idx >> 4, jl = idx & 15;
            float pi = G[bl * 68 + jl]      + sP[bl * 64 + jl];
            float pf = G[bl * 68 + 16 + jl] + sP[bl * 64 + 16 + jl];
            float pg = G[bl * 68 + 32 + jl] + sP[bl * 64 + 32 + jl];
            float po = G[bl * 68 + 48 + jl] + sP[bl * 64 + 48 + jl];
            float ig = sigm(pi);
            float fg = sigm(pf);
            float gg = tanh_fast(pg);
            float og = sigm(po);
            float cn = fg * creg[e] + ig * gg;
            creg[e] = cn;
            hnext[(size_t)(b0 + bl) * Hh + j0 + jl] = rtf(og * tanh_fast(cn));
        }

        if (t != Tt - 1) {
            __syncthreads();     // all h stores of this CTA done
            if (tid == 0) {
                __threadfence(); // h stores -> L2 before signal
                atomicAdd(&g_sig[grp][jg][0], 1u);
            }
        }
        hb = hbn;
    }
}

// ---------------- final FC: out[b][n] = h_last[b,:]·W_fc[n,:] + b_fc[n] ----------------
__global__ void fc_kernel(const float* __restrict__ Wfc,
                          const float* __restrict__ bfc,
                          float* __restrict__ out) {
    int w = (blockIdx.x * blockDim.x + threadIdx.x) >> 5;
    int lane = threadIdx.x & 31;
    int b = w >> 7, n = w & 127;
    const float* hr = g_h[2] + (size_t)b * Hh;              // t=511 wrote g_h[512%3=2]
    const float* wr = Wfc + (size_t)n * Hh;
    float s = 0.f;
    for (int k = lane; k < Hh; k += 32) s += hr[k] * wr[k];
#pragma unroll
    for (int off = 16; off; off >>= 1) s += __shfl_xor_sync(0xffffffffu, s, off);
    if (lane == 0) out[b * NC + n] = s + bfc[n];
}

// ---------------- launch ----------------
extern "C" void kernel_launch(void* const* d_in, const int* in_sizes, int n_in,
                              void* d_out, int out_size) {
    (void)in_sizes; (void)n_in; (void)out_size;
    const float* x   = (const float*)d_in[0];
    const float* Wih = (const float*)d_in[1];
    const float* Whh = (const float*)d_in[2];
    const float* bih = (const float*)d_in[3];
    const float* bhh = (const float*)d_in[4];
    const float* Wfc = (const float*)d_in[5];
    const float* bfc = (const float*)d_in[6];
    float* out = (float*)d_out;

    const int smem_p1 = STAGES * (64 + 128) * PADW * 4;   // 110592
    cudaFuncSetAttribute(phase1_kernel, cudaFuncAttributeMaxDynamicSharedMemorySize, smem_p1);
    cudaFuncSetAttribute(lstm_persist,  cudaFuncAttributeMaxDynamicSharedMemorySize, SMEM_REC);

    prep_kernel<<<2048, 256>>>(x, Wih, Whh);
    phase1_kernel<<<dim3(16, 2048), 256, smem_p1>>>(bih, bhh);
    lstm_persist<<<dim3(32, 4), 256, SMEM_REC>>>();
    fc_kernel<<<4096, 256>>>(Wfc, bfc, out);
}

// round 16
// speedup vs baseline: 1.1316x; 1.0560x over previous
#include <cuda_runtime.h>
#include <cuda_bf16.h>
#include <cstdint>
#include <math.h>

#define Bsz 256
#define Tt  512
#define Din 256
#define Hh  512
#define G4  2048
#define NC  128

// phase-1 pipeline params
#define STAGES 4
#define KC     32
#define PADW   36    // 32+4 pad: row pitch 144B == 16 mod 128 -> conflict-free ldmatrix

// recurrence pipeline params
#define STG2   4
#define KC2    64
#define PADW2  68    // 64+4 pad: row pitch 272B == 16 mod 128 -> conflict-free ldmatrix
#define WPAD   516   // 512+4 pad for persistent W slice
#define NGRP   32    // CTAs per b-tile barrier group

// ---------------- static device scratch (no allocations allowed) ----------------
__device__ __align__(128) float g_P[(size_t)Tt * Bsz * G4];   // x-projection + biases, [t][b][g]
__device__ __align__(128) float g_xr[(size_t)Bsz * Tt * Din]; // tf32-rounded x
__device__ __align__(128) float g_Wih[G4 * Din];              // tf32-rounded W_ih
__device__ __align__(128) float g_Whh[G4 * Hh];               // tf32-rounded W_hh
__device__ __align__(128) float g_h[2][Bsz * Hh];             // ping-pong hidden state

// per-b-tile barrier state: 4 groups, each on its own 128B line.
__device__ __align__(128) unsigned g_bars[4][32];

// ---------------- helpers ----------------
__device__ __forceinline__ float rtf(float x) {
    unsigned u;
    asm("cvt.rna.tf32.f32 %0, %1;" : "=r"(u) : "f"(x));
    return __uint_as_float(u);
}

__device__ __forceinline__ void mma_tf32(float (&c)[4], const unsigned (&a)[4],
                                         unsigned b0, unsigned b1) {
    asm volatile(
        "mma.sync.aligned.m16n8k8.row.col.f32.tf32.tf32.f32 "
        "{%0,%1,%2,%3}, {%4,%5,%6,%7}, {%8,%9}, {%0,%1,%2,%3};\n"
        : "+f"(c[0]), "+f"(c[1]), "+f"(c[2]), "+f"(c[3])
        : "r"(a[0]), "r"(a[1]), "r"(a[2]), "r"(a[3]), "r"(b0), "r"(b1));
}

// ldmatrix x4: loads the tf32 m16n8k8 A fragment (16x8 f32 tile == 16x16 b16 view).
// Lane l supplies row (base + (l&15)), float-col offset (l>>4)*4.
__device__ __forceinline__ void ldsm4(unsigned& r0, unsigned& r1, unsigned& r2, unsigned& r3,
                                      uint32_t addr) {
    asm volatile("ldmatrix.sync.aligned.m8n8.x4.shared.b16 {%0,%1,%2,%3}, [%4];"
                 : "=r"(r0), "=r"(r1), "=r"(r2), "=r"(r3) : "r"(addr));
}

__device__ __forceinline__ void cpa16(uint32_t s, const void* g) {
    asm volatile("cp.async.cg.shared.global [%0], [%1], 16;\n" :: "r"(s), "l"(g));
}
__device__ __forceinline__ void cpa_commit() {
    asm volatile("cp.async.commit_group;\n");
}
template<int N> __device__ __forceinline__ void cpa_wait() {
    asm volatile("cp.async.wait_group %0;\n" :: "n"(N));
}

__device__ __forceinline__ float sigm(float x) { return 1.f / (1.f + __expf(-x)); }
__device__ __forceinline__ float tanh_fast(float x) { return 1.f - 2.f / (__expf(2.f * x) + 1.f); }

// barrier among the 32 CTAs sharing one b-tile (all 128 CTAs co-resident).
__device__ __forceinline__ void group_barrier(int grp, unsigned gen_next) {
    __syncthreads();
    if (threadIdx.x == 0) {
        __threadfence();
        unsigned t = atomicAdd(&g_bars[grp][0], 1);
        if (t == NGRP - 1) {
            g_bars[grp][0] = 0;
            __threadfence();
            *(volatile unsigned*)&g_bars[grp][1] = gen_next;
        } else {
            while (*(volatile unsigned*)&g_bars[grp][1] < gen_next) { __nanosleep(64); }
            __threadfence();
        }
    }
    __syncthreads();
}

// dummy launch: shifts the ncu capture index (which has landed on fc_kernel every
// run) so it should now land on lstm_persist. Negligible cost.
__global__ void dummy_kernel() {}

// ---------------- prep: round inputs to tf32, zero state, reset barriers ----------------
__global__ void prep_kernel(const float* __restrict__ x,
                            const float* __restrict__ Wih,
                            const float* __restrict__ Whh) {
    size_t i = (size_t)blockIdx.x * blockDim.x + threadIdx.x;
    size_t stride = (size_t)gridDim.x * blockDim.x;
    if (i == 0) {
        for (int g = 0; g < 4; g++) { g_bars[g][0] = 0; g_bars[g][1] = 0; }
    }
    for (size_t k = i; k < (size_t)Bsz * Tt * Din; k += stride) g_xr[k]  = rtf(x[k]);
    for (size_t k = i; k < (size_t)G4 * Din;       k += stride) g_Wih[k] = rtf(Wih[k]);
    for (size_t k = i; k < (size_t)G4 * Hh;        k += stride) g_Whh[k] = rtf(Whh[k]);
    for (size_t k = i; k < (size_t)Bsz * Hh;       k += stride) g_h[0][k] = 0.f;
}

// ---------------- phase 1: P[t][b][g] = x[b,t,:]·W_ih[g,:] + b_ih[g] + b_hh[g] ----------------
__global__ void __launch_bounds__(256) phase1_kernel(const float* __restrict__ bih,
                                                     const float* __restrict__ bhh) {
    extern __shared__ float sm[];
    float* sB = sm + STAGES * 64 * PADW;
    uint32_t smem_u32 = (uint32_t)__cvta_generic_to_shared(sm);
    uint32_t sA_b = smem_u32;
    uint32_t sB_b = smem_u32 + STAGES * 64 * PADW * 4;

    const int tid = threadIdx.x;
    const int g0 = blockIdx.x * 128;
    const int r0 = blockIdx.y * 64;
    const int NCH = Din / KC;  // 8

    auto load_chunk = [&](int kk, int stage) {
        const int kb = kk * KC;
#pragma unroll
        for (int i = 0; i < 2; i++) {           // A: 64x32 = 512 float4
            int v = tid + i * 256;
            int row = v >> 3, q = v & 7;
            int r = r0 + row;
            int b = r & 255, t = r >> 8;
            const float* src = g_xr + ((size_t)b * Tt + t) * Din + kb + q * 4;
            cpa16(sA_b + (uint32_t)((stage * 64 * PADW + row * PADW + q * 4) * 4), src);
        }
#pragma unroll
        for (int i = 0; i < 4; i++) {           // B: 128x32 = 1024 float4
            int v = tid + i * 256;
            int r = v >> 3, q = v & 7;
            const float* src = g_Wih + (size_t)(g0 + r) * Din + kb + q * 4;
            cpa16(sB_b + (uint32_t)((stage * 128 * PADW + r * PADW + q * 4) * 4), src);
        }
        cpa_commit();
    };

    const int lane = tid & 31, wid = tid >> 5;
    const int gid = lane >> 2, tig = lane & 3;
    const int m0 = (wid >> 2) * 32, n0 = (wid & 3) * 32;
    // ldmatrix per-lane offset within the A tile (floats): row (lane&15), col (lane>>4)*4
    const int lmoff = (lane & 15) * PADW + (lane >> 4) * 4;

    float acc[2][4][4] = {};

    load_chunk(0, 0); load_chunk(1, 1); load_chunk(2, 2);
    for (int kk = 0; kk < NCH; kk++) {
        if (kk < NCH - 2)       cpa_wait<2>();
        else if (kk == NCH - 2) cpa_wait<1>();
        else                    cpa_wait<0>();
        __syncthreads();
        if (kk + 3 < NCH) load_chunk(kk + 3, (kk + 3) % STAGES);

        uint32_t cA_b = sA_b + (uint32_t)((kk % STAGES) * 64 * PADW * 4);
        const float* cB = sB + (kk % STAGES) * 128 * PADW;
#pragma unroll
        for (int k8 = 0; k8 < KC / 8; k8++) {
            const int kb = k8 * 8;
            unsigned a[2][4];
#pragma unroll
            for (int mt = 0; mt < 2; mt++) {    // one ldmatrix.x4 replaces 4 scalar LDS
                uint32_t addr = cA_b + (uint32_t)(((m0 + mt * 16) * PADW + lmoff + kb) * 4);
                ldsm4(a[mt][0], a[mt][1], a[mt][2], a[mt][3], addr);
            }
#pragma unroll
            for (int nt = 0; nt < 4; nt++) {
                int cr = n0 + nt * 8 + gid;
                unsigned b0 = __float_as_uint(cB[cr * PADW + kb + tig]);
                unsigned b1 = __float_as_uint(cB[cr * PADW + kb + tig + 4]);
                mma_tf32(acc[0][nt], a[0], b0, b1);
                mma_tf32(acc[1][nt], a[1], b0, b1);
            }
        }
    }

    // epilogue: add biases, store to g_P (float2 stores; cols are even)
#pragma unroll
    for (int nt = 0; nt < 4; nt++) {
        int col = n0 + nt * 8 + tig * 2;
        float bv0 = bih[g0 + col] + bhh[g0 + col];
        float bv1 = bih[g0 + col + 1] + bhh[g0 + col + 1];
#pragma unroll
        for (int mt = 0; mt < 2; mt++) {
            int row = m0 + mt * 16 + gid;
            float2 v0 = make_float2(acc[mt][nt][0] + bv0, acc[mt][nt][1] + bv1);
            float2 v1 = make_float2(acc[mt][nt][2] + bv0, acc[mt][nt][3] + bv1);
            *reinterpret_cast<float2*>(&g_P[(size_t)(r0 + row) * G4 + g0 + col]) = v0;
            *reinterpret_cast<float2*>(&g_P[(size_t)(r0 + row + 8) * G4 + g0 + col]) = v1;
        }
    }
}

// ---------------- persistent LSTM recurrence (R7 base + ldmatrix A loads) ----------------
// 128 CTAs (32 j-tiles of 16 x 4 b-tiles of 64), 256 threads (8 warps 2x4).
// W slice persistent in SMEM; h via cp.async (KC2=64, 4-stage, 8 chunks); per-b-tile
// group barriers; P[t+1] prefetched to registers before the barrier.
__global__ void __launch_bounds__(256) lstm_persist() {
    extern __shared__ float sm[];
    float* sW = sm + STG2 * 64 * PADW2;         // 64 x WPAD persistent W slice
    uint32_t smem_u32 = (uint32_t)__cvta_generic_to_shared(sm);
    uint32_t sA_b = smem_u32;

    const int tid = threadIdx.x;
    const int j0 = blockIdx.x * 16;
    const int b0 = blockIdx.y * 64;
    const int grp = blockIdx.y;
    const int NCH = Hh / KC2;                   // 8

    const int lane = tid & 31, wid = tid >> 5;
    const int gid = lane >> 2, tig = lane & 3;
    const int m0 = (wid >> 2) * 32;
    const int n0 = (wid & 3) * 16;
    const int lmoff = (lane & 15) * PADW2 + (lane >> 4) * 4;   // ldmatrix lane offset

    const int ebl = tid >> 4;
    const int ejl = tid & 15;

    // one-time: W slice [64 rows x 512], row = gate*16 + jj
    for (int v = tid; v < 64 * 128; v += 256) {
        int r = v >> 7, q = v & 127;
        int gate = r >> 4, jj = r & 15;
        float4 s = *reinterpret_cast<const float4*>(
            g_Whh + (size_t)(gate * Hh + j0 + jj) * Hh + q * 4);
        *reinterpret_cast<float4*>(&sW[r * WPAD + q * 4]) = s;
    }
    __syncthreads();

    float creg[4] = {};      // register-resident cell state
    float pp[4][4];          // current step's P (prefetched ahead of use)

    auto prefetch_P = [&](int t, float (&dst)[4][4]) {
        const float* Pt = g_P + (size_t)t * Bsz * G4;
#pragma unroll
        for (int e = 0; e < 4; e++) {
            int bl = ebl + e * 16;
            const float* pbase = Pt + (size_t)(b0 + bl) * G4 + j0 + ejl;
            dst[e][0] = pbase[0];
            dst[e][1] = pbase[512];
            dst[e][2] = pbase[1024];
            dst[e][3] = pbase[1536];
        }
    };

    prefetch_P(0, pp);

    for (int t = 0; t < Tt; t++) {
        const float* __restrict__ hprev = g_h[t & 1];
        float* __restrict__ hnext = g_h[(t + 1) & 1];

        auto load_chunk = [&](int kk, int stage) {
            const int kb = kk * KC2;
#pragma unroll
            for (int i = 0; i < 4; i++) {       // A = h tile: 64x64 = 1024 float4
                int v = tid + i * 256;
                int row = v >> 4, q = v & 15;
                const float* src = hprev + (size_t)(b0 + row) * Hh + kb + q * 4;
                cpa16(sA_b + (uint32_t)((stage * 64 * PADW2 + row * PADW2 + q * 4) * 4), src);
            }
            cpa_commit();
        };

        float acc[2][2][4] = {};

        load_chunk(0, 0); load_chunk(1, 1); load_chunk(2, 2);
        for (int kk = 0; kk < NCH; kk++) {
            if (kk < NCH - 2)       cpa_wait<2>();
            else if (kk == NCH - 2) cpa_wait<1>();
            else                    cpa_wait<0>();
            __syncthreads();
            if (kk + 3 < NCH) load_chunk(kk + 3, (kk + 3) % STG2);

            uint32_t cA_b = sA_b + (uint32_t)((kk % STG2) * 64 * PADW2 * 4);
            const float* cW = sW + kk * KC2;
#pragma unroll
            for (int k8 = 0; k8 < KC2 / 8; k8++) {
                const int kb = k8 * 8;
                unsigned a[2][4];
#pragma unroll
                for (int mt = 0; mt < 2; mt++) {   // one ldmatrix.x4 per m-tile
                    uint32_t addr = cA_b + (uint32_t)(((m0 + mt * 16) * PADW2 + lmoff + kb) * 4);
                    ldsm4(a[mt][0], a[mt][1], a[mt][2], a[mt][3], addr);
                }
#pragma unroll
                for (int nt = 0; nt < 2; nt++) {
                    int cr = n0 + nt * 8 + gid;
                    unsigned b0r = __float_as_uint(cW[cr * WPAD + kb + tig]);
                    unsigned b1r = __float_as_uint(cW[cr * WPAD + kb + tig + 4]);
                    mma_tf32(acc[0][nt], a[0], b0r, b1r);
                    mma_tf32(acc[1][nt], a[1], b0r, b1r);
                }
            }
        }

        __syncthreads();         // GEMM done (wait<0> drained); reuse A region as G[64][68]
        float* G = sm;
#pragma unroll
        for (int mt = 0; mt < 2; mt++)
#pragma unroll
            for (int nt = 0; nt < 2; nt++) {
                int row = m0 + mt * 16 + gid, col = n0 + nt * 8 + tig * 2;
                G[row * 68 + col]           = acc[mt][nt][0];
                G[row * 68 + col + 1]       = acc[mt][nt][1];
                G[(row + 8) * 68 + col]     = acc[mt][nt][2];
                G[(row + 8) * 68 + col + 1] = acc[mt][nt][3];
            }
        __syncthreads();

        // elementwise LSTM update: 64 b x 16 j = 1024 pairs, 4 per thread
#pragma unroll
        for (int e = 0; e < 4; e++) {
            int bl = ebl + e * 16;
            float pi = G[bl * 68 + ejl]        + pp[e][0];
            float pf = G[bl * 68 + 16 + ejl]   + pp[e][1];
            float pg = G[bl * 68 + 32 + ejl]   + pp[e][2];
            float po = G[bl * 68 + 48 + ejl]   + pp[e][3];
            float ig = sigm(pi);
            float fg = sigm(pf);
            float gg = tanh_fast(pg);
            float og = sigm(po);
            float cn = fg * creg[e] + ig * gg;
            creg[e] = cn;
            size_t ci = (size_t)(b0 + bl) * Hh + j0 + ejl;
            hnext[ci] = rtf(og * tanh_fast(cn));  // tf32-round: next step's mma operand
        }

        if (t != Tt - 1) {
            prefetch_P(t + 1, pp);   // DRAM latency overlaps the barrier wait
            group_barrier(grp, (unsigned)(t + 1));
        }
    }
}

// ---------------- final FC: out[b][n] = h_last[b,:]·W_fc[n,:] + b_fc[n] ----------------
__global__ void fc_kernel(const float* __restrict__ Wfc,
                          const float* __restrict__ bfc,
                          float* __restrict__ out) {
    int w = (blockIdx.x * blockDim.x + threadIdx.x) >> 5;
    int lane = threadIdx.x & 31;
    int b = w >> 7, n = w & 127;
    const float* hr = g_h[0] + (size_t)b * Hh;              // t=511 wrote g_h[0]
    const float* wr = Wfc + (size_t)n * Hh;
    float s = 0.f;
    for (int k = lane; k < Hh; k += 32) s += hr[k] * wr[k];
#pragma unroll
    for (int off = 16; off; off >>= 1) s += __shfl_xor_sync(0xffffffffu, s, off);
    if (lane == 0) out[b * NC + n] = s + bfc[n];
}

// ---------------- launch ----------------
extern "C" void kernel_launch(void* const* d_in, const int* in_sizes, int n_in,
                              void* d_out, int out_size) {
    (void)in_sizes; (void)n_in; (void)out_size;
    const float* x   = (const float*)d_in[0];
    const float* Wih = (const float*)d_in[1];
    const float* Whh = (const float*)d_in[2];
    const float* bih = (const float*)d_in[3];
    const float* bhh = (const float*)d_in[4];
    const float* Wfc = (const float*)d_in[5];
    const float* bfc = (const float*)d_in[6];
    float* out = (float*)d_out;

    const int smem_p1 = STAGES * (64 + 128) * PADW * 4;               // 110592
    const int smem_rec = (STG2 * 64 * PADW2 + 64 * WPAD) * 4;         // 69632 + 132096 = 201728
    cudaFuncSetAttribute(phase1_kernel, cudaFuncAttributeMaxDynamicSharedMemorySize, smem_p1);
    cudaFuncSetAttribute(lstm_persist,  cudaFuncAttributeMaxDynamicSharedMemorySize, smem_rec);

    dummy_kernel<<<1, 32>>>();   // shifts ncu capture index toward lstm_persist
    prep_kernel<<<2048, 256>>>(x, Wih, Whh);
    phase1_kernel<<<dim3(16, 2048), 256, smem_p1>>>(bih, bhh);
    lstm_persist<<<dim3(32, 4), 256, smem_rec>>>();
    fc_kernel<<<4096, 256>>>(Wfc, bfc, out);
}